// round 14
// baseline (speedup 1.0000x reference)
#include <cuda_runtime.h>

#define N_NODES 1048576
#define N_EDGES (4 * N_NODES)

typedef unsigned long long u64;

// Scratch accumulator: per-node (sum0,sum1,sum2,count). Zeroed by prep_kernel
// at the start of every call (zero-init at load makes call 0 identical).
// 32B-aligned for 256-bit ld/st.
__device__ __align__(32) float4 g_scr[N_NODES];
// Padded x table: one 16B row per node -> single-wavefront gathers.
__device__ __align__(32) float4 g_x4[N_NODES];

__device__ __forceinline__ u64 fma2(u64 a, u64 b, u64 c) {
    u64 d;
    asm("fma.rn.f32x2 %0, %1, %2, %3;" : "=l"(d) : "l"(a), "l"(b), "l"(c));
    return d;
}
__device__ __forceinline__ u64 pack2(float lo, float hi) {
    u64 d;
    asm("mov.b64 %0, {%1, %2};" : "=l"(d) : "f"(lo), "f"(hi));
    return d;
}
__device__ __forceinline__ void unpack2(u64 a, float& lo, float& hi) {
    asm("mov.b64 {%0, %1}, %2;" : "=f"(lo), "=f"(hi) : "l"(a));
}
__device__ __forceinline__ u64 relu2(u64 a) {
    float lo, hi;
    unpack2(a, lo, hi);
    return pack2(fmaxf(lo, 0.f), fmaxf(hi, 0.f));
}

// 256-bit global loads (sm_100+). Pointer must be 32B-aligned.
__device__ __forceinline__ void ld256f(const float4* p, float4& a, float4& b) {
    asm volatile("ld.global.v8.f32 {%0,%1,%2,%3,%4,%5,%6,%7}, [%8];"
                 : "=f"(a.x), "=f"(a.y), "=f"(a.z), "=f"(a.w),
                   "=f"(b.x), "=f"(b.y), "=f"(b.z), "=f"(b.w)
                 : "l"(p));
}
__device__ __forceinline__ void ld256i(const int* p, int4& a, int4& b) {
    asm volatile("ld.global.v8.b32 {%0,%1,%2,%3,%4,%5,%6,%7}, [%8];"
                 : "=r"(a.x), "=r"(a.y), "=r"(a.z), "=r"(a.w),
                   "=r"(b.x), "=r"(b.y), "=r"(b.z), "=r"(b.w)
                 : "l"(p));
}
__device__ __forceinline__ void ld256e(const float* p, float4& a, float4& b) {
    asm volatile("ld.global.v8.f32 {%0,%1,%2,%3,%4,%5,%6,%7}, [%8];"
                 : "=f"(a.x), "=f"(a.y), "=f"(a.z), "=f"(a.w),
                   "=f"(b.x), "=f"(b.y), "=f"(b.z), "=f"(b.w)
                 : "l"(p));
}

// Pad x[N,3] -> g_x4 via smem transpose, and zero g_scr. One node per thread.
__global__ void __launch_bounds__(256) prep_kernel(const float4* __restrict__ x) {
    __shared__ float sx[768];
    int t = threadIdx.x;
    if (t < 192) {
        float4 v = x[blockIdx.x * 192 + t];
        *(float4*)&sx[4 * t] = v;
    }
    __syncthreads();
    int node = blockIdx.x * 256 + t;
    // stride-3 float reads: 3 coprime to 32 banks -> conflict-free
    g_x4[node] = make_float4(sx[3 * t], sx[3 * t + 1], sx[3 * t + 2], 0.f);
    g_scr[node] = make_float4(0.f, 0.f, 0.f, 0.f);
}

// Edge MLP + scatter-add. EIGHT edges per thread, FOUR packed f32x2 streams.
// Streams loaded with 256-bit ld.global.v8.
__global__ void __launch_bounds__(256, 3) edge_kernel(
        const int*   __restrict__ ei,
        const float* __restrict__ eattr,
        const float* __restrict__ w1a,
        const float* __restrict__ b1a,
        const float* __restrict__ w1b,
        const float* __restrict__ b1b) {
    // per hidden j: [wx, wy | wz, ww | bias, v0 | v1, v2], pairs 16B-aligned.
    __shared__ __align__(16) u64 sw[20][8];
    int t = threadIdx.x;
    if (t < 20) {
        sw[t][0] = pack2(w1a[t],          w1a[t]);
        sw[t][1] = pack2(w1a[20 + t],     w1a[20 + t]);
        sw[t][2] = pack2(w1a[40 + t],     w1a[40 + t]);
        sw[t][3] = pack2(w1a[60 + t],     w1a[60 + t]);
        sw[t][4] = pack2(b1a[t],          b1a[t]);
        sw[t][5] = pack2(w1b[3 * t],      w1b[3 * t]);
        sw[t][6] = pack2(w1b[3 * t + 1],  w1b[3 * t + 1]);
        sw[t][7] = pack2(w1b[3 * t + 2],  w1b[3 * t + 2]);
    }
    __syncthreads();

    int e = (blockIdx.x * 256 + t) * 8;
    if (e >= N_EDGES) return;

    int4 rr1, rr2, cc1, cc2;
    float4 ef1, ef2;
    ld256i(ei + e, rr1, rr2);                // sources A..H (32B-aligned)
    ld256i(ei + N_EDGES + e, cc1, cc2);      // dests A..H
    ld256e(eattr + e, ef1, ef2);

    // 8 single-wavefront gathers issued back-to-back (MLP=8).
    float4 xa = __ldg(&g_x4[rr1.x]);
    float4 xb = __ldg(&g_x4[rr1.y]);
    float4 xc = __ldg(&g_x4[rr1.z]);
    float4 xd = __ldg(&g_x4[rr1.w]);
    float4 xe = __ldg(&g_x4[rr2.x]);
    float4 xf = __ldg(&g_x4[rr2.y]);
    float4 xg = __ldg(&g_x4[rr2.z]);
    float4 xh = __ldg(&g_x4[rr2.w]);

    u64 X0ab = pack2(xa.x, xb.x), X0cd = pack2(xc.x, xd.x);
    u64 X1ab = pack2(xa.y, xb.y), X1cd = pack2(xc.y, xd.y);
    u64 X2ab = pack2(xa.z, xb.z), X2cd = pack2(xc.z, xd.z);
    u64 X0ef = pack2(xe.x, xf.x), X0gh = pack2(xg.x, xh.x);
    u64 X1ef = pack2(xe.y, xf.y), X1gh = pack2(xg.y, xh.y);
    u64 X2ef = pack2(xe.z, xf.z), X2gh = pack2(xg.z, xh.z);
    u64 EAab = pack2(ef1.x, ef1.y), EAcd = pack2(ef1.z, ef1.w);
    u64 EAef = pack2(ef2.x, ef2.y), EAgh = pack2(ef2.z, ef2.w);

    float bb0 = b1b[0], bb1 = b1b[1], bb2 = b1b[2];
    u64 o0ab = pack2(bb0, bb0), o0cd = o0ab, o0ef = o0ab, o0gh = o0ab;
    u64 o1ab = pack2(bb1, bb1), o1cd = o1ab, o1ef = o1ab, o1gh = o1ab;
    u64 o2ab = pack2(bb2, bb2), o2cd = o2ab, o2ef = o2ab, o2gh = o2ab;

#pragma unroll
    for (int j = 0; j < 20; j++) {
        const ulonglong2* wp = (const ulonglong2*)sw[j];
        ulonglong2 w01 = wp[0];
        ulonglong2 w23 = wp[1];
        ulonglong2 w45 = wp[2];
        ulonglong2 w67 = wp[3];
        u64 hab = fma2(X0ab, w01.x, fma2(X1ab, w01.y, fma2(X2ab, w23.x, fma2(EAab, w23.y, w45.x))));
        u64 hcd = fma2(X0cd, w01.x, fma2(X1cd, w01.y, fma2(X2cd, w23.x, fma2(EAcd, w23.y, w45.x))));
        u64 hef = fma2(X0ef, w01.x, fma2(X1ef, w01.y, fma2(X2ef, w23.x, fma2(EAef, w23.y, w45.x))));
        u64 hgh = fma2(X0gh, w01.x, fma2(X1gh, w01.y, fma2(X2gh, w23.x, fma2(EAgh, w23.y, w45.x))));
        hab = relu2(hab);
        hcd = relu2(hcd);
        hef = relu2(hef);
        hgh = relu2(hgh);
        o0ab = fma2(hab, w45.y, o0ab);  o0cd = fma2(hcd, w45.y, o0cd);
        o0ef = fma2(hef, w45.y, o0ef);  o0gh = fma2(hgh, w45.y, o0gh);
        o1ab = fma2(hab, w67.x, o1ab);  o1cd = fma2(hcd, w67.x, o1cd);
        o1ef = fma2(hef, w67.x, o1ef);  o1gh = fma2(hgh, w67.x, o1gh);
        o2ab = fma2(hab, w67.y, o2ab);  o2cd = fma2(hcd, w67.y, o2cd);
        o2ef = fma2(hef, w67.y, o2ef);  o2gh = fma2(hgh, w67.y, o2gh);
    }

    float pA0, pB0, pA1, pB1, pA2, pB2;
    float pC0, pD0, pC1, pD1, pC2, pD2;
    unpack2(o0ab, pA0, pB0); unpack2(o1ab, pA1, pB1); unpack2(o2ab, pA2, pB2);
    unpack2(o0cd, pC0, pD0); unpack2(o1cd, pC1, pD1); unpack2(o2cd, pC2, pD2);

    asm volatile("red.global.add.v4.f32 [%0], {%1, %2, %3, %4};"
                 :: "l"(g_scr + cc1.x), "f"(pA0), "f"(pA1), "f"(pA2), "f"(1.0f) : "memory");
    asm volatile("red.global.add.v4.f32 [%0], {%1, %2, %3, %4};"
                 :: "l"(g_scr + cc1.y), "f"(pB0), "f"(pB1), "f"(pB2), "f"(1.0f) : "memory");
    asm volatile("red.global.add.v4.f32 [%0], {%1, %2, %3, %4};"
                 :: "l"(g_scr + cc1.z), "f"(pC0), "f"(pC1), "f"(pC2), "f"(1.0f) : "memory");
    asm volatile("red.global.add.v4.f32 [%0], {%1, %2, %3, %4};"
                 :: "l"(g_scr + cc1.w), "f"(pD0), "f"(pD1), "f"(pD2), "f"(1.0f) : "memory");

    float pE0, pF0, pE1, pF1, pE2, pF2;
    float pG0, pH0, pG1, pH1, pG2, pH2;
    unpack2(o0ef, pE0, pF0); unpack2(o1ef, pE1, pF1); unpack2(o2ef, pE2, pF2);
    unpack2(o0gh, pG0, pH0); unpack2(o1gh, pG1, pH1); unpack2(o2gh, pG2, pH2);

    asm volatile("red.global.add.v4.f32 [%0], {%1, %2, %3, %4};"
                 :: "l"(g_scr + cc2.x), "f"(pE0), "f"(pE1), "f"(pE2), "f"(1.0f) : "memory");
    asm volatile("red.global.add.v4.f32 [%0], {%1, %2, %3, %4};"
                 :: "l"(g_scr + cc2.y), "f"(pF0), "f"(pF1), "f"(pF2), "f"(1.0f) : "memory");
    asm volatile("red.global.add.v4.f32 [%0], {%1, %2, %3, %4};"
                 :: "l"(g_scr + cc2.z), "f"(pG0), "f"(pG1), "f"(pG2), "f"(1.0f) : "memory");
    asm volatile("red.global.add.v4.f32 [%0], {%1, %2, %3, %4};"
                 :: "l"(g_scr + cc2.w), "f"(pH0), "f"(pH1), "f"(pH2), "f"(1.0f) : "memory");
}

// Node MLP + L2 normalize. FOUR nodes per thread.
// g_scr read with two 256-bit loads. __launch_bounds__(256, 4): 4 blocks/SM.
__global__ void __launch_bounds__(256, 4) node_kernel(
        const float* __restrict__ x,
        const float* __restrict__ w2a,
        const float* __restrict__ b2a,
        const float* __restrict__ w2b,
        const float* __restrict__ b2b,
        float* __restrict__ out) {
    // per hidden j: [w0,w1 | w2,w3 | w4,w5 | bias,v0 | v1,v2], pairs 16B-aligned.
    __shared__ __align__(16) u64 sw[20][10];
    int t = threadIdx.x;
    if (t < 20) {
        sw[t][0] = pack2(w2a[t],           w2a[t]);
        sw[t][1] = pack2(w2a[20 + t],      w2a[20 + t]);
        sw[t][2] = pack2(w2a[40 + t],      w2a[40 + t]);
        sw[t][3] = pack2(w2a[60 + t],      w2a[60 + t]);
        sw[t][4] = pack2(w2a[80 + t],      w2a[80 + t]);
        sw[t][5] = pack2(w2a[100 + t],     w2a[100 + t]);
        sw[t][6] = pack2(b2a[t],           b2a[t]);
        sw[t][7] = pack2(w2b[3 * t],       w2b[3 * t]);
        sw[t][8] = pack2(w2b[3 * t + 1],   w2b[3 * t + 1]);
        sw[t][9] = pack2(w2b[3 * t + 2],   w2b[3 * t + 2]);
    }
    __syncthreads();

    int i = (blockIdx.x * 256 + t) * 4;
    if (i >= N_NODES) return;

    float4 sA, sB, sC, sD;
    ld256f(g_scr + i, sA, sB);        // 64B-aligned (i % 4 == 0)
    ld256f(g_scr + i + 2, sC, sD);
    const float4* px = (const float4*)(x + 3 * i);
    float4 xv0 = px[0];  // A.x A.y A.z B.x
    float4 xv1 = px[1];  // B.y B.z C.x C.y
    float4 xv2 = px[2];  // C.z D.x D.y D.z

    float invA = 1.0f / fmaxf(sA.w, 1.0f);
    float invB = 1.0f / fmaxf(sB.w, 1.0f);
    float invC = 1.0f / fmaxf(sC.w, 1.0f);
    float invD = 1.0f / fmaxf(sD.w, 1.0f);

    u64 X0ab = pack2(xv0.x, xv0.w), X0cd = pack2(xv1.z, xv2.y);
    u64 X1ab = pack2(xv0.y, xv1.x), X1cd = pack2(xv1.w, xv2.z);
    u64 X2ab = pack2(xv0.z, xv1.y), X2cd = pack2(xv2.x, xv2.w);
    u64 A0ab = pack2(sA.x * invA, sB.x * invB), A0cd = pack2(sC.x * invC, sD.x * invD);
    u64 A1ab = pack2(sA.y * invA, sB.y * invB), A1cd = pack2(sC.y * invC, sD.y * invD);
    u64 A2ab = pack2(sA.z * invA, sB.z * invB), A2cd = pack2(sC.z * invC, sD.z * invD);

    float bb0 = b2b[0], bb1 = b2b[1], bb2 = b2b[2];
    u64 o0ab = pack2(bb0, bb0), o0cd = o0ab;
    u64 o1ab = pack2(bb1, bb1), o1cd = o1ab;
    u64 o2ab = pack2(bb2, bb2), o2cd = o2ab;

#pragma unroll
    for (int j = 0; j < 20; j++) {
        const ulonglong2* wp = (const ulonglong2*)sw[j];
        ulonglong2 w01 = wp[0];
        ulonglong2 w23 = wp[1];
        ulonglong2 w45 = wp[2];
        ulonglong2 w67 = wp[3];
        ulonglong2 w89 = wp[4];
        u64 hab = fma2(X0ab, w01.x,
                  fma2(X1ab, w01.y,
                  fma2(X2ab, w23.x,
                  fma2(A0ab, w23.y,
                  fma2(A1ab, w45.x,
                  fma2(A2ab, w45.y, w67.x))))));
        u64 hcd = fma2(X0cd, w01.x,
                  fma2(X1cd, w01.y,
                  fma2(X2cd, w23.x,
                  fma2(A0cd, w23.y,
                  fma2(A1cd, w45.x,
                  fma2(A2cd, w45.y, w67.x))))));
        hab = relu2(hab);
        hcd = relu2(hcd);
        o0ab = fma2(hab, w67.y, o0ab);  o0cd = fma2(hcd, w67.y, o0cd);
        o1ab = fma2(hab, w89.x, o1ab);  o1cd = fma2(hcd, w89.x, o1cd);
        o2ab = fma2(hab, w89.y, o2ab);  o2cd = fma2(hcd, w89.y, o2cd);
    }

    float pA0, pB0, pA1, pB1, pA2, pB2;
    float pC0, pD0, pC1, pD1, pC2, pD2;
    unpack2(o0ab, pA0, pB0); unpack2(o1ab, pA1, pB1); unpack2(o2ab, pA2, pB2);
    unpack2(o0cd, pC0, pD0); unpack2(o1cd, pC1, pD1); unpack2(o2cd, pC2, pD2);

    float facA = rsqrtf(pA0 * pA0 + pA1 * pA1 + pA2 * pA2);
    float facB = rsqrtf(pB0 * pB0 + pB1 * pB1 + pB2 * pB2);
    float facC = rsqrtf(pC0 * pC0 + pC1 * pC1 + pC2 * pC2);
    float facD = rsqrtf(pD0 * pD0 + pD1 * pD1 + pD2 * pD2);

    float4* o = (float4*)(out + 3 * i);
    o[0] = make_float4(pA0 * facA, pA1 * facA, pA2 * facA, pB0 * facB);
    o[1] = make_float4(pB1 * facB, pB2 * facB, pC0 * facC, pC1 * facC);
    o[2] = make_float4(pC2 * facC, pD0 * facD, pD1 * facD, pD2 * facD);
}

extern "C" void kernel_launch(void* const* d_in, const int* in_sizes, int n_in,
                              void* d_out, int out_size) {
    // 0:x 1:edge_index 2:edge_attr 3:u 4:batch
    // 5:w1a 6:b1a 7:w1b 8:b1b 9:w2a 10:b2a 11:w2b 12:b2b
    const float* x     = (const float*)d_in[0];
    const int*   ei    = (const int*)  d_in[1];
    const float* eattr = (const float*)d_in[2];
    const float* w1a   = (const float*)d_in[5];
    const float* b1a   = (const float*)d_in[6];
    const float* w1b   = (const float*)d_in[7];
    const float* b1b   = (const float*)d_in[8];
    const float* w2a   = (const float*)d_in[9];
    const float* b2a   = (const float*)d_in[10];
    const float* w2b   = (const float*)d_in[11];
    const float* b2b   = (const float*)d_in[12];
    float* out = (float*)d_out;

    prep_kernel<<<N_NODES / 256, 256>>>((const float4*)x);
    edge_kernel<<<N_EDGES / 2048, 256>>>(ei, eattr, w1a, b1a, w1b, b1b);
    node_kernel<<<N_NODES / 1024, 256>>>(x, w2a, b2a, w2b, b2b, out);
}

// round 15
// speedup vs baseline: 1.0319x; 1.0319x over previous
#include <cuda_runtime.h>

#define N_NODES 1048576
#define N_EDGES (4 * N_NODES)

typedef unsigned long long u64;

// Scratch accumulator: per-node (sum0,sum1,sum2,count). Zeroed by prep_kernel
// at the start of every call (zero-init at load makes call 0 identical).
__device__ float4 g_scr[N_NODES];
// Padded x table: one 16B row per node -> single-wavefront gathers.
__device__ float4 g_x4[N_NODES];

__device__ __forceinline__ u64 fma2(u64 a, u64 b, u64 c) {
    u64 d;
    asm("fma.rn.f32x2 %0, %1, %2, %3;" : "=l"(d) : "l"(a), "l"(b), "l"(c));
    return d;
}
__device__ __forceinline__ u64 pack2(float lo, float hi) {
    u64 d;
    asm("mov.b64 %0, {%1, %2};" : "=l"(d) : "f"(lo), "f"(hi));
    return d;
}
__device__ __forceinline__ void unpack2(u64 a, float& lo, float& hi) {
    asm("mov.b64 {%0, %1}, %2;" : "=f"(lo), "=f"(hi) : "l"(a));
}
__device__ __forceinline__ u64 relu2(u64 a) {
    float lo, hi;
    unpack2(a, lo, hi);
    return pack2(fmaxf(lo, 0.f), fmaxf(hi, 0.f));
}

// L2-only gather (no L1 allocation): the 16MB table has ~1.4% L1 hit rate,
// so L1 line fills are pure overhead in the L1tex-bound edge kernel.
__device__ __forceinline__ float4 ldcg4(const float4* p) {
    float4 v;
    asm volatile("ld.global.cg.v4.f32 {%0,%1,%2,%3}, [%4];"
                 : "=f"(v.x), "=f"(v.y), "=f"(v.z), "=f"(v.w) : "l"(p));
    return v;
}

// Pad x[N,3] -> g_x4 via smem transpose, and zero g_scr. One node per thread.
__global__ void __launch_bounds__(256) prep_kernel(const float4* __restrict__ x) {
    __shared__ float sx[768];
    int t = threadIdx.x;
    if (t < 192) {
        float4 v = x[blockIdx.x * 192 + t];
        *(float4*)&sx[4 * t] = v;
    }
    __syncthreads();
    int node = blockIdx.x * 256 + t;
    // stride-3 float reads: 3 coprime to 32 banks -> conflict-free
    g_x4[node] = make_float4(sx[3 * t], sx[3 * t + 1], sx[3 * t + 2], 0.f);
    g_scr[node] = make_float4(0.f, 0.f, 0.f, 0.f);
}

// Edge MLP + scatter-add. EIGHT edges per thread, FOUR packed f32x2 streams
// sharing one weight-load per loop iteration. Gathers are L2-only.
__global__ void __launch_bounds__(256, 3) edge_kernel(
        const int*   __restrict__ ei,
        const float* __restrict__ eattr,
        const float* __restrict__ w1a,
        const float* __restrict__ b1a,
        const float* __restrict__ w1b,
        const float* __restrict__ b1b) {
    // per hidden j: [wx, wy | wz, ww | bias, v0 | v1, v2], pairs 16B-aligned.
    __shared__ __align__(16) u64 sw[20][8];
    int t = threadIdx.x;
    if (t < 20) {
        sw[t][0] = pack2(w1a[t],          w1a[t]);
        sw[t][1] = pack2(w1a[20 + t],     w1a[20 + t]);
        sw[t][2] = pack2(w1a[40 + t],     w1a[40 + t]);
        sw[t][3] = pack2(w1a[60 + t],     w1a[60 + t]);
        sw[t][4] = pack2(b1a[t],          b1a[t]);
        sw[t][5] = pack2(w1b[3 * t],      w1b[3 * t]);
        sw[t][6] = pack2(w1b[3 * t + 1],  w1b[3 * t + 1]);
        sw[t][7] = pack2(w1b[3 * t + 2],  w1b[3 * t + 2]);
    }
    __syncthreads();

    int e = (blockIdx.x * 256 + t) * 8;
    if (e >= N_EDGES) return;

    int4   rr1 = *(const int4*)(ei + e);                 // sources A..D
    int4   rr2 = *(const int4*)(ei + e + 4);             // sources E..H
    int4   cc1 = *(const int4*)(ei + N_EDGES + e);       // dests A..D
    int4   cc2 = *(const int4*)(ei + N_EDGES + e + 4);   // dests E..H
    float4 ef1 = *(const float4*)(eattr + e);
    float4 ef2 = *(const float4*)(eattr + e + 4);

    // 8 single-wavefront L2-only gathers issued back-to-back (MLP=8).
    float4 xa = ldcg4(&g_x4[rr1.x]);
    float4 xb = ldcg4(&g_x4[rr1.y]);
    float4 xc = ldcg4(&g_x4[rr1.z]);
    float4 xd = ldcg4(&g_x4[rr1.w]);
    float4 xe = ldcg4(&g_x4[rr2.x]);
    float4 xf = ldcg4(&g_x4[rr2.y]);
    float4 xg = ldcg4(&g_x4[rr2.z]);
    float4 xh = ldcg4(&g_x4[rr2.w]);

    u64 X0ab = pack2(xa.x, xb.x), X0cd = pack2(xc.x, xd.x);
    u64 X1ab = pack2(xa.y, xb.y), X1cd = pack2(xc.y, xd.y);
    u64 X2ab = pack2(xa.z, xb.z), X2cd = pack2(xc.z, xd.z);
    u64 X0ef = pack2(xe.x, xf.x), X0gh = pack2(xg.x, xh.x);
    u64 X1ef = pack2(xe.y, xf.y), X1gh = pack2(xg.y, xh.y);
    u64 X2ef = pack2(xe.z, xf.z), X2gh = pack2(xg.z, xh.z);
    u64 EAab = pack2(ef1.x, ef1.y), EAcd = pack2(ef1.z, ef1.w);
    u64 EAef = pack2(ef2.x, ef2.y), EAgh = pack2(ef2.z, ef2.w);

    float bb0 = b1b[0], bb1 = b1b[1], bb2 = b1b[2];
    u64 o0ab = pack2(bb0, bb0), o0cd = o0ab, o0ef = o0ab, o0gh = o0ab;
    u64 o1ab = pack2(bb1, bb1), o1cd = o1ab, o1ef = o1ab, o1gh = o1ab;
    u64 o2ab = pack2(bb2, bb2), o2cd = o2ab, o2ef = o2ab, o2gh = o2ab;

#pragma unroll
    for (int j = 0; j < 20; j++) {
        const ulonglong2* wp = (const ulonglong2*)sw[j];
        ulonglong2 w01 = wp[0];   // wx, wy
        ulonglong2 w23 = wp[1];   // wz, ww
        ulonglong2 w45 = wp[2];   // bias, v0
        ulonglong2 w67 = wp[3];   // v1, v2
        u64 hab = fma2(X0ab, w01.x, fma2(X1ab, w01.y, fma2(X2ab, w23.x, fma2(EAab, w23.y, w45.x))));
        u64 hcd = fma2(X0cd, w01.x, fma2(X1cd, w01.y, fma2(X2cd, w23.x, fma2(EAcd, w23.y, w45.x))));
        u64 hef = fma2(X0ef, w01.x, fma2(X1ef, w01.y, fma2(X2ef, w23.x, fma2(EAef, w23.y, w45.x))));
        u64 hgh = fma2(X0gh, w01.x, fma2(X1gh, w01.y, fma2(X2gh, w23.x, fma2(EAgh, w23.y, w45.x))));
        hab = relu2(hab);
        hcd = relu2(hcd);
        hef = relu2(hef);
        hgh = relu2(hgh);
        o0ab = fma2(hab, w45.y, o0ab);  o0cd = fma2(hcd, w45.y, o0cd);
        o0ef = fma2(hef, w45.y, o0ef);  o0gh = fma2(hgh, w45.y, o0gh);
        o1ab = fma2(hab, w67.x, o1ab);  o1cd = fma2(hcd, w67.x, o1cd);
        o1ef = fma2(hef, w67.x, o1ef);  o1gh = fma2(hgh, w67.x, o1gh);
        o2ab = fma2(hab, w67.y, o2ab);  o2cd = fma2(hcd, w67.y, o2cd);
        o2ef = fma2(hef, w67.y, o2ef);  o2gh = fma2(hgh, w67.y, o2gh);
    }

    float pA0, pB0, pA1, pB1, pA2, pB2;
    float pC0, pD0, pC1, pD1, pC2, pD2;
    unpack2(o0ab, pA0, pB0); unpack2(o1ab, pA1, pB1); unpack2(o2ab, pA2, pB2);
    unpack2(o0cd, pC0, pD0); unpack2(o1cd, pC1, pD1); unpack2(o2cd, pC2, pD2);

    asm volatile("red.global.add.v4.f32 [%0], {%1, %2, %3, %4};"
                 :: "l"(g_scr + cc1.x), "f"(pA0), "f"(pA1), "f"(pA2), "f"(1.0f) : "memory");
    asm volatile("red.global.add.v4.f32 [%0], {%1, %2, %3, %4};"
                 :: "l"(g_scr + cc1.y), "f"(pB0), "f"(pB1), "f"(pB2), "f"(1.0f) : "memory");
    asm volatile("red.global.add.v4.f32 [%0], {%1, %2, %3, %4};"
                 :: "l"(g_scr + cc1.z), "f"(pC0), "f"(pC1), "f"(pC2), "f"(1.0f) : "memory");
    asm volatile("red.global.add.v4.f32 [%0], {%1, %2, %3, %4};"
                 :: "l"(g_scr + cc1.w), "f"(pD0), "f"(pD1), "f"(pD2), "f"(1.0f) : "memory");

    float pE0, pF0, pE1, pF1, pE2, pF2;
    float pG0, pH0, pG1, pH1, pG2, pH2;
    unpack2(o0ef, pE0, pF0); unpack2(o1ef, pE1, pF1); unpack2(o2ef, pE2, pF2);
    unpack2(o0gh, pG0, pH0); unpack2(o1gh, pG1, pH1); unpack2(o2gh, pG2, pH2);

    asm volatile("red.global.add.v4.f32 [%0], {%1, %2, %3, %4};"
                 :: "l"(g_scr + cc2.x), "f"(pE0), "f"(pE1), "f"(pE2), "f"(1.0f) : "memory");
    asm volatile("red.global.add.v4.f32 [%0], {%1, %2, %3, %4};"
                 :: "l"(g_scr + cc2.y), "f"(pF0), "f"(pF1), "f"(pF2), "f"(1.0f) : "memory");
    asm volatile("red.global.add.v4.f32 [%0], {%1, %2, %3, %4};"
                 :: "l"(g_scr + cc2.z), "f"(pG0), "f"(pG1), "f"(pG2), "f"(1.0f) : "memory");
    asm volatile("red.global.add.v4.f32 [%0], {%1, %2, %3, %4};"
                 :: "l"(g_scr + cc2.w), "f"(pH0), "f"(pH1), "f"(pH2), "f"(1.0f) : "memory");
}

// Node MLP + L2 normalize. FOUR nodes per thread (R13 best form).
// __launch_bounds__(256, 4): cap regs at 64 -> 4 blocks/SM.
__global__ void __launch_bounds__(256, 4) node_kernel(
        const float* __restrict__ x,
        const float* __restrict__ w2a,
        const float* __restrict__ b2a,
        const float* __restrict__ w2b,
        const float* __restrict__ b2b,
        float* __restrict__ out) {
    // per hidden j: [w0,w1 | w2,w3 | w4,w5 | bias,v0 | v1,v2], pairs 16B-aligned.
    __shared__ __align__(16) u64 sw[20][10];
    int t = threadIdx.x;
    if (t < 20) {
        sw[t][0] = pack2(w2a[t],           w2a[t]);
        sw[t][1] = pack2(w2a[20 + t],      w2a[20 + t]);
        sw[t][2] = pack2(w2a[40 + t],      w2a[40 + t]);
        sw[t][3] = pack2(w2a[60 + t],      w2a[60 + t]);
        sw[t][4] = pack2(w2a[80 + t],      w2a[80 + t]);
        sw[t][5] = pack2(w2a[100 + t],     w2a[100 + t]);
        sw[t][6] = pack2(b2a[t],           b2a[t]);
        sw[t][7] = pack2(w2b[3 * t],       w2b[3 * t]);
        sw[t][8] = pack2(w2b[3 * t + 1],   w2b[3 * t + 1]);
        sw[t][9] = pack2(w2b[3 * t + 2],   w2b[3 * t + 2]);
    }
    __syncthreads();

    int i = (blockIdx.x * 256 + t) * 4;
    if (i >= N_NODES) return;

    float4 sA = g_scr[i];
    float4 sB = g_scr[i + 1];
    float4 sC = g_scr[i + 2];
    float4 sD = g_scr[i + 3];
    const float4* px = (const float4*)(x + 3 * i);
    float4 xv0 = px[0];  // A.x A.y A.z B.x
    float4 xv1 = px[1];  // B.y B.z C.x C.y
    float4 xv2 = px[2];  // C.z D.x D.y D.z

    float invA = 1.0f / fmaxf(sA.w, 1.0f);
    float invB = 1.0f / fmaxf(sB.w, 1.0f);
    float invC = 1.0f / fmaxf(sC.w, 1.0f);
    float invD = 1.0f / fmaxf(sD.w, 1.0f);

    u64 X0ab = pack2(xv0.x, xv0.w), X0cd = pack2(xv1.z, xv2.y);
    u64 X1ab = pack2(xv0.y, xv1.x), X1cd = pack2(xv1.w, xv2.z);
    u64 X2ab = pack2(xv0.z, xv1.y), X2cd = pack2(xv2.x, xv2.w);
    u64 A0ab = pack2(sA.x * invA, sB.x * invB), A0cd = pack2(sC.x * invC, sD.x * invD);
    u64 A1ab = pack2(sA.y * invA, sB.y * invB), A1cd = pack2(sC.y * invC, sD.y * invD);
    u64 A2ab = pack2(sA.z * invA, sB.z * invB), A2cd = pack2(sC.z * invC, sD.z * invD);

    float bb0 = b2b[0], bb1 = b2b[1], bb2 = b2b[2];
    u64 o0ab = pack2(bb0, bb0), o0cd = o0ab;
    u64 o1ab = pack2(bb1, bb1), o1cd = o1ab;
    u64 o2ab = pack2(bb2, bb2), o2cd = o2ab;

#pragma unroll
    for (int j = 0; j < 20; j++) {
        const ulonglong2* wp = (const ulonglong2*)sw[j];
        ulonglong2 w01 = wp[0];
        ulonglong2 w23 = wp[1];
        ulonglong2 w45 = wp[2];
        ulonglong2 w67 = wp[3];
        ulonglong2 w89 = wp[4];
        u64 hab = fma2(X0ab, w01.x,
                  fma2(X1ab, w01.y,
                  fma2(X2ab, w23.x,
                  fma2(A0ab, w23.y,
                  fma2(A1ab, w45.x,
                  fma2(A2ab, w45.y, w67.x))))));
        u64 hcd = fma2(X0cd, w01.x,
                  fma2(X1cd, w01.y,
                  fma2(X2cd, w23.x,
                  fma2(A0cd, w23.y,
                  fma2(A1cd, w45.x,
                  fma2(A2cd, w45.y, w67.x))))));
        hab = relu2(hab);
        hcd = relu2(hcd);
        o0ab = fma2(hab, w67.y, o0ab);  o0cd = fma2(hcd, w67.y, o0cd);
        o1ab = fma2(hab, w89.x, o1ab);  o1cd = fma2(hcd, w89.x, o1cd);
        o2ab = fma2(hab, w89.y, o2ab);  o2cd = fma2(hcd, w89.y, o2cd);
    }

    float pA0, pB0, pA1, pB1, pA2, pB2;
    float pC0, pD0, pC1, pD1, pC2, pD2;
    unpack2(o0ab, pA0, pB0); unpack2(o1ab, pA1, pB1); unpack2(o2ab, pA2, pB2);
    unpack2(o0cd, pC0, pD0); unpack2(o1cd, pC1, pD1); unpack2(o2cd, pC2, pD2);

    float facA = rsqrtf(pA0 * pA0 + pA1 * pA1 + pA2 * pA2);
    float facB = rsqrtf(pB0 * pB0 + pB1 * pB1 + pB2 * pB2);
    float facC = rsqrtf(pC0 * pC0 + pC1 * pC1 + pC2 * pC2);
    float facD = rsqrtf(pD0 * pD0 + pD1 * pD1 + pD2 * pD2);

    float4* o = (float4*)(out + 3 * i);
    o[0] = make_float4(pA0 * facA, pA1 * facA, pA2 * facA, pB0 * facB);
    o[1] = make_float4(pB1 * facB, pB2 * facB, pC0 * facC, pC1 * facC);
    o[2] = make_float4(pC2 * facC, pD0 * facD, pD1 * facD, pD2 * facD);
}

extern "C" void kernel_launch(void* const* d_in, const int* in_sizes, int n_in,
                              void* d_out, int out_size) {
    // 0:x 1:edge_index 2:edge_attr 3:u 4:batch
    // 5:w1a 6:b1a 7:w1b 8:b1b 9:w2a 10:b2a 11:w2b 12:b2b
    const float* x     = (const float*)d_in[0];
    const int*   ei    = (const int*)  d_in[1];
    const float* eattr = (const float*)d_in[2];
    const float* w1a   = (const float*)d_in[5];
    const float* b1a   = (const float*)d_in[6];
    const float* w1b   = (const float*)d_in[7];
    const float* b1b   = (const float*)d_in[8];
    const float* w2a   = (const float*)d_in[9];
    const float* b2a   = (const float*)d_in[10];
    const float* w2b   = (const float*)d_in[11];
    const float* b2b   = (const float*)d_in[12];
    float* out = (float*)d_out;

    prep_kernel<<<N_NODES / 256, 256>>>((const float4*)x);
    edge_kernel<<<N_EDGES / 2048, 256>>>(ei, eattr, w1a, b1a, w1b, b1b);
    node_kernel<<<N_NODES / 1024, 256>>>(x, w2a, b2a, w2b, b2b, out);
}